// round 14
// baseline (speedup 1.0000x reference)
#include <cuda_runtime.h>
#include <cuda_fp16.h>
#include <cstdint>

// Problem constants (fixed-shape problem)
#define NN      50000
#define EE_MAX  800000
#define GG      128
#define DINF    200
#define DHF     128
#define NLAY    4
#define BN_EPS  1e-5f
#define OUTW    (DINF + NLAY * DHF)   // 712
#define WPAIRS  548
#define APK_W   50
#define NTILES  ((NN + 63) / 64)      // 782
#define BNP_CH  16                    // rows per bnpool chunk

// ---------------- scratch (device globals; no allocation allowed) ----------
__device__ uint4    g_apk    [NN * APK_W];
__device__ float    g_mid    [NN * DHF];
__device__ float    g_rep    [NN * DHF];
__device__ uint2    g_hh     [NN * (DHF / 4)];    // h as packed fp16 (4 per uint2)
__device__ uint2    g_xh     [NN * (DINF / 4)];   // x as packed fp16
__device__ int      g_cnt    [2 * NN];
__device__ int      g_rowptr [NN + 1];
__device__ int      g_colidx [EE_MAX];
__device__ float    g_sum    [2 * NLAY][DHF];
__device__ float    g_sumsq  [2 * NLAY][DHF];
__device__ uint32_t g_wpk    [WPAIRS * DHF];      // fp16x2 of W pair-rows
__device__ unsigned g_bar_cnt;
__device__ unsigned g_bar_gen;

// ---------------- device-wide barrier (all blocks resident) ----------------
__device__ __forceinline__ void grid_sync() {
    __syncthreads();
    if (threadIdx.x == 0) {
        unsigned gen = *(volatile unsigned*)&g_bar_gen;
        __threadfence();
        unsigned ticket = atomicAdd(&g_bar_cnt, 1u);
        if (ticket == gridDim.x - 1) {
            g_bar_cnt = 0u;
            __threadfence();
            atomicAdd(&g_bar_gen, 1u);
        } else {
            while (*(volatile unsigned*)&g_bar_gen == gen) __nanosleep(64);
        }
        __threadfence();
    }
    __syncthreads();
}

// ---------------- fp16 helpers ----------------------------------------------
__device__ __forceinline__ uint32_t pack_f16(float v0, float v1, float& rem0, float& rem1) {
    __half h0 = __float2half_rn(v0);
    __half h1 = __float2half_rn(v1);
    rem0 = v0 - __half2float(h0);
    rem1 = v1 - __half2float(h1);
    return ((uint32_t)__half_as_ushort(h1) << 16) | (uint32_t)__half_as_ushort(h0);
}
__device__ __forceinline__ uint32_t pack_f16_rn(float v0, float v1) {
    __half2 p = __floats2half2_rn(v0, v1);   // .x = v0 (low half)
    return *(uint32_t*)&p;
}
__device__ __forceinline__ float4 h4_to_f4(uint2 u) {
    __half2 a = *(__half2*)&u.x;
    __half2 b = *(__half2*)&u.y;
    float2 fa = __half22float2(a);
    float2 fb = __half22float2(b);
    return make_float4(fa.x, fa.y, fb.x, fb.y);
}

// -------- weight prepack + x->fp16 + hist zero + out zero ------------------
__global__ void k_packw(const float* __restrict__ w1_0, const float* __restrict__ w2_0,
                        const float* __restrict__ w1_r, const float* __restrict__ w2_r,
                        const float* __restrict__ x,
                        float* __restrict__ out, int out_n) {
    int b = blockIdx.x;
    int c = threadIdx.x;
    int gtid = b * DHF + c;
    const int stride = WPAIRS * DHF;
    for (int i = gtid; i < NN; i += stride) g_cnt[i] = 0;
    for (int i = gtid; i < out_n; i += stride) out[i] = 0.f;
    // x -> packed fp16 (NN*100 uint words)
    uint32_t* xp = (uint32_t*)g_xh;
    for (int i = gtid; i < NN * (DINF / 2); i += stride)
        xp[i] = pack_f16_rn(x[2 * i], x[2 * i + 1]);

    const float* src;
    int kp;
    if (b < 100)      { src = w1_0; kp = b; }
    else if (b < 164) { src = w2_0; kp = b - 100; }
    else {
        int r = b - 164;
        if (r < 192) { src = w1_r + (r / 64) * DHF * DHF; kp = r % 64; }
        else { r -= 192; src = w2_r + (r / 64) * DHF * DHF; kp = r % 64; }
    }
    float v0 = src[(size_t)(2 * kp) * DHF + c];
    float v1 = src[(size_t)(2 * kp + 1) * DHF + c];
    g_wpk[b * DHF + c] = pack_f16_rn(v0, v1);
}

// ---------------- CSR build ------------------------------------------------
__global__ void k_hist(const int* __restrict__ erow, int E) {
    int e = blockIdx.x * blockDim.x + threadIdx.x;
    if (e < E) atomicAdd(&g_cnt[erow[e]], 1);
}

__global__ void k_scan_big() {
    extern __shared__ int sc[];
    int* part = sc + NN;
    const int T = 1024;
    int t = threadIdx.x;

    if (t < DHF) {
        for (int l = 0; l < 2 * NLAY; l++) { g_sum[l][t] = 0.f; g_sumsq[l][t] = 0.f; }
    }
    for (int i = t; i < NN; i += T) {
        sc[i] = g_cnt[i];
        g_cnt[NN + i] = 0;
    }
    __syncthreads();

    const int C = (NN + T - 1) / T;
    int base = t * C;
    int s = 0;
    for (int j = 0; j < C; j++) {
        int i = base + j;
        if (i < NN) s += sc[i];
    }
    part[t] = s;
    __syncthreads();
    for (int off = 1; off < T; off <<= 1) {
        int v = (t >= off) ? part[t - off] : 0;
        __syncthreads();
        part[t] += v;
        __syncthreads();
    }
    int pre = (t > 0) ? part[t - 1] : 0;
    for (int j = 0; j < C; j++) {
        int i = base + j;
        if (i < NN) {
            int c = sc[i];
            sc[i] = pre;
            pre += c;
        }
    }
    __syncthreads();
    for (int i = t; i < NN; i += T) g_rowptr[i] = sc[i];
    if (t == T - 1) g_rowptr[NN] = pre;
}

__global__ void k_scatter(const int* __restrict__ erow, const int* __restrict__ ecol, int E) {
    int e = blockIdx.x * blockDim.x + threadIdx.x;
    if (e < E) {
        int r = erow[e];
        int p = g_rowptr[r] + atomicAdd(&g_cnt[NN + r], 1);
        g_colidx[p] = ecol[e];
    }
}

// ---------------- fused layer kernel phases ---------------------------------
__device__ __forceinline__ void mma16(float* c, const uint32_t* a, const uint32_t* b) {
    asm volatile(
        "mma.sync.aligned.m16n8k16.row.col.f32.f16.f16.f32 "
        "{%0,%1,%2,%3}, {%4,%5,%6,%7}, {%8,%9}, {%0,%1,%2,%3};"
        : "+f"(c[0]), "+f"(c[1]), "+f"(c[2]), "+f"(c[3])
        : "r"(a[0]), "r"(a[1]), "r"(a[2]), "r"(a[3]), "r"(b[0]), "r"(b[1]));
}

struct GemmSmem {
    uint32_t ash[2][8][72], asl[2][8][72];
    uint32_t wsh[2][8][136];
    float strs[DHF], strh[DHF];
};

// phase A: spmm over fp16-packed features (uint2 = 4 halves per gather unit)
template <int D4>
__device__ void spmm_phase(const uint2* __restrict__ hin, uint4* __restrict__ pout,
                           float se) {
    const int S = (D4 + 31) / 32;
    int lane = threadIdx.x & 31;
    int wstride = gridDim.x * 8;
    for (int wid = blockIdx.x * 8 + (threadIdx.x >> 5); wid < NN; wid += wstride) {
        const uint2* selfr = hin + (size_t)wid * D4;
        float4 acc[S];
#pragma unroll
        for (int s = 0; s < S; s++) {
            int j = lane + 32 * s;
            if (j < D4) {
                float4 v = h4_to_f4(selfr[j]);
                acc[s] = make_float4(v.x * se, v.y * se, v.z * se, v.w * se);
            } else acc[s] = make_float4(0.f, 0.f, 0.f, 0.f);
        }
        int e0 = g_rowptr[wid], e1 = g_rowptr[wid + 1];
        int e = e0;
        for (; e + 4 <= e1; e += 4) {
            int c0 = g_colidx[e], c1 = g_colidx[e + 1];
            int c2 = g_colidx[e + 2], c3 = g_colidx[e + 3];
            const uint2* r0 = hin + (size_t)c0 * D4;
            const uint2* r1 = hin + (size_t)c1 * D4;
            const uint2* r2 = hin + (size_t)c2 * D4;
            const uint2* r3 = hin + (size_t)c3 * D4;
#pragma unroll
            for (int s = 0; s < S; s++) {
                int j = lane + 32 * s;
                if (j < D4) {
                    float4 v0 = h4_to_f4(r0[j]);
                    float4 v1 = h4_to_f4(r1[j]);
                    float4 v2 = h4_to_f4(r2[j]);
                    float4 v3 = h4_to_f4(r3[j]);
                    acc[s].x += (v0.x + v1.x) + (v2.x + v3.x);
                    acc[s].y += (v0.y + v1.y) + (v2.y + v3.y);
                    acc[s].z += (v0.z + v1.z) + (v2.z + v3.z);
                    acc[s].w += (v0.w + v1.w) + (v2.w + v3.w);
                }
            }
        }
        for (; e < e1; e++) {
            int c = g_colidx[e];
            const uint2* r = hin + (size_t)c * D4;
#pragma unroll
            for (int s = 0; s < S; s++) {
                int j = lane + 32 * s;
                if (j < D4) {
                    float4 v = h4_to_f4(r[j]);
                    acc[s].x += v.x; acc[s].y += v.y; acc[s].z += v.z; acc[s].w += v.w;
                }
            }
        }
        uint4* o = pout + (size_t)wid * D4;
#pragma unroll
        for (int s = 0; s < S; s++) {
            int j = lane + 32 * s;
            if (j < D4) {
                float r0, r1, r2, r3;
                uint32_t h01 = pack_f16(acc[s].x, acc[s].y, r0, r1);
                uint32_t h23 = pack_f16(acc[s].z, acc[s].w, r2, r3);
                o[j] = make_uint4(h01, h23, pack_f16_rn(r0, r1), pack_f16_rn(r2, r3));
            }
        }
    }
}

// GEMM phase: 64-row tiles strided by block; 2-term fp16 split.
template <int PACKED>
__device__ void gemm_phase(GemmSmem& sm,
                           const float* __restrict__ A, const uint4* __restrict__ Apk,
                           const uint32_t* __restrict__ wpk,
                           const float* __restrict__ bias, float* __restrict__ C, int K,
                           const float* __restrict__ bnga, const float* __restrict__ bnbe,
                           const float* __restrict__ psum, const float* __restrict__ psq,
                           float* __restrict__ osum, float* __restrict__ osumsq) {
    const int tid  = threadIdx.x;
    const int lane = tid & 31;
    const int wid  = tid >> 5;
    const int wr   = wid >> 2;
    const int wc   = wid & 3;
    const int gid  = lane >> 2;
    const int tq   = lane & 3;
    const int arA = tid & 63;
    const int kgA = tid >> 6;
    const int arW = tid & 127;
    const int kgW = tid >> 7;
    const int KP  = K >> 1;
    const int KP4 = K >> 2;
    const int T   = (K + 15) >> 4;

    if (!PACKED) {
        if (tid < DHF) {
            const float invN = 1.0f / NN;
            float m = psum[tid] * invN;
            float v = psq[tid] * invN - m * m;
            float sc = bnga[tid] * rsqrtf(v + BN_EPS);
            sm.strs[tid] = sc;
            sm.strh[tid] = bnbe[tid] - m * sc;
        }
        __syncthreads();
    }

    for (int tile = blockIdx.x; tile < NTILES; tile += gridDim.x) {
        const int row0 = tile * 64;
        const int grA  = row0 + arA;
        const bool rokA = (grA < NN);

        float acc[2][4][4];
#pragma unroll
        for (int mt = 0; mt < 2; mt++)
#pragma unroll
            for (int nt = 0; nt < 4; nt++)
#pragma unroll
                for (int j = 0; j < 4; j++) acc[mt][nt][j] = 0.f;

        float4 va;
        uint4 pa;
        uint32_t wk[4];

        auto prefetch = [&](int t) {
            if (PACKED) {
                int gp = t * 4 + kgA;
                pa = make_uint4(0u, 0u, 0u, 0u);
                if (rokA && gp < KP4) pa = Apk[(size_t)grA * KP4 + gp];
            } else {
                int gk0 = t * 16 + 4 * kgA;
                va = make_float4(0.f, 0.f, 0.f, 0.f);
                if (rokA && gk0 < K) va = *(const float4*)&A[(size_t)grA * K + gk0];
            }
#pragma unroll
            for (int j = 0; j < 4; j++) {
                int kp = t * 8 + kgW + 2 * j;
                wk[j] = (kp < KP) ? wpk[kp * DHF + arW] : 0u;
            }
        };

        auto stage = [&](int d, int k0) {
            if (PACKED) {
                sm.ash[d][2 * kgA][arA]     = pa.x;
                sm.ash[d][2 * kgA + 1][arA] = pa.y;
                sm.asl[d][2 * kgA][arA]     = pa.z;
                sm.asl[d][2 * kgA + 1][arA] = pa.w;
            } else {
                float a4[4] = {va.x, va.y, va.z, va.w};
                if (rokA) {
#pragma unroll
                    for (int j = 0; j < 4; j++) {
                        int gk = k0 + 4 * kgA + j;
                        a4[j] = (gk < K) ? fmaxf(a4[j] * sm.strs[gk] + sm.strh[gk], 0.f) : 0.f;
                    }
                }
#pragma unroll
                for (int p = 0; p < 2; p++) {
                    float r0f, r1f;
                    sm.ash[d][2 * kgA + p][arA] = pack_f16(a4[2 * p], a4[2 * p + 1], r0f, r1f);
                    sm.asl[d][2 * kgA + p][arA] = pack_f16_rn(r0f, r1f);
                }
            }
#pragma unroll
            for (int j = 0; j < 4; j++)
                sm.wsh[d][kgW + 2 * j][arW] = wk[j];
        };

        prefetch(0);
        stage(0, 0);
        __syncthreads();

        for (int t = 0; t < T; t++) {
            const int cur = t & 1;
            if (t + 1 < T) prefetch(t + 1);
            {
                uint32_t bh[4][2];
#pragma unroll
                for (int nt = 0; nt < 4; nt++) {
                    int col = wc * 32 + nt * 8 + gid;
                    bh[nt][0] = sm.wsh[cur][tq][col];
                    bh[nt][1] = sm.wsh[cur][tq + 4][col];
                }
#pragma unroll
                for (int mt = 0; mt < 2; mt++) {
                    int r0 = wr * 32 + mt * 16;
                    uint32_t ah[4], al[4];
                    ah[0] = sm.ash[cur][tq][r0 + gid];
                    ah[1] = sm.ash[cur][tq][r0 + gid + 8];
                    ah[2] = sm.ash[cur][tq + 4][r0 + gid];
                    ah[3] = sm.ash[cur][tq + 4][r0 + gid + 8];
                    al[0] = sm.asl[cur][tq][r0 + gid];
                    al[1] = sm.asl[cur][tq][r0 + gid + 8];
                    al[2] = sm.asl[cur][tq + 4][r0 + gid];
                    al[3] = sm.asl[cur][tq + 4][r0 + gid + 8];
#pragma unroll
                    for (int nt = 0; nt < 4; nt++) {
                        mma16(acc[mt][nt], ah, bh[nt]);   // hiA * W
                        mma16(acc[mt][nt], al, bh[nt]);   // loA * W
                    }
                }
            }
            if (t + 1 < T) stage((t + 1) & 1, (t + 1) * 16);
            __syncthreads();
        }

        // epilogue: bias, store, column stats
        float cs[4][2], cq[4][2];
#pragma unroll
        for (int nt = 0; nt < 4; nt++)
#pragma unroll
            for (int j = 0; j < 2; j++) { cs[nt][j] = 0.f; cq[nt][j] = 0.f; }

#pragma unroll
        for (int mt = 0; mt < 2; mt++) {
            int rbase = row0 + wr * 32 + mt * 16;
#pragma unroll
            for (int nt = 0; nt < 4; nt++) {
                int colb = wc * 32 + nt * 8 + 2 * tq;
                float b0 = bias[colb], b1 = bias[colb + 1];
                int r1 = rbase + gid;
                int r2 = rbase + gid + 8;
                if (r1 < NN) {
                    float v0 = acc[mt][nt][0] + b0;
                    float v1 = acc[mt][nt][1] + b1;
                    *(float2*)&C[(size_t)r1 * 128 + colb] = make_float2(v0, v1);
                    cs[nt][0] += v0; cq[nt][0] += v0 * v0;
                    cs[nt][1] += v1; cq[nt][1] += v1 * v1;
                }
                if (r2 < NN) {
                    float v0 = acc[mt][nt][2] + b0;
                    float v1 = acc[mt][nt][3] + b1;
                    *(float2*)&C[(size_t)r2 * 128 + colb] = make_float2(v0, v1);
                    cs[nt][0] += v0; cq[nt][0] += v0 * v0;
                    cs[nt][1] += v1; cq[nt][1] += v1 * v1;
                }
            }
        }
#pragma unroll
        for (int nt = 0; nt < 4; nt++)
#pragma unroll
            for (int j = 0; j < 2; j++) {
                float s = cs[nt][j], q = cq[nt][j];
                s += __shfl_xor_sync(0xffffffffu, s, 4);
                s += __shfl_xor_sync(0xffffffffu, s, 8);
                s += __shfl_xor_sync(0xffffffffu, s, 16);
                q += __shfl_xor_sync(0xffffffffu, q, 4);
                q += __shfl_xor_sync(0xffffffffu, q, 8);
                q += __shfl_xor_sync(0xffffffffu, q, 16);
                if (gid == 0) {
                    int col = wc * 32 + nt * 8 + 2 * tq + j;
                    atomicAdd(&osum[col], s);
                    atomicAdd(&osumsq[col], q);
                }
            }
        __syncthreads();
    }
}

// phase D: BN+ReLU+pool; writes h as packed fp16 pairs (shfl to pair columns)
__device__ void bnpool_phase(const float* __restrict__ rep,
                             float* __restrict__ out, int off,
                             const float* __restrict__ gamma, const float* __restrict__ beta,
                             const int* __restrict__ gids, int slot, int write_h) {
    int c = threadIdx.x & 127;
    int half = threadIdx.x >> 7;
    const float invN = 1.0f / NN;
    float m = g_sum[slot][c] * invN;
    float v = g_sumsq[slot][c] * invN - m * m;
    float sc = gamma[c] * rsqrtf(v + BN_EPS);
    float sh = beta[c] - m * sc;
    uint32_t* hp = (uint32_t*)g_hh;

    const int nch = NN / BNP_CH;   // 3125 exact
    for (int cc = blockIdx.x * 2 + half; cc < nch; cc += gridDim.x * 2) {
        int r0 = cc * BNP_CH;
        float vals[BNP_CH];
        int gv[BNP_CH];
#pragma unroll
        for (int i = 0; i < BNP_CH; i++) {
            vals[i] = rep[(size_t)(r0 + i) * DHF + c];
            gv[i] = gids[r0 + i];
        }
#pragma unroll
        for (int i = 0; i < BNP_CH; i++)
            vals[i] = fmaxf(vals[i] * sc + sh, 0.f);
        if (write_h) {
#pragma unroll
            for (int i = 0; i < BNP_CH; i++) {
                float vn = __shfl_down_sync(0xffffffffu, vals[i], 1);
                if ((c & 1) == 0)
                    hp[(size_t)(r0 + i) * (DHF / 2) + (c >> 1)] = pack_f16_rn(vals[i], vn);
            }
        }
        int curg = gv[0];
        float acc = 0.f;
#pragma unroll
        for (int i = 0; i < BNP_CH; i++) {
            if (gv[i] != curg) {
                atomicAdd(&out[(size_t)curg * OUTW + off + c], acc);
                acc = 0.f;
                curg = gv[i];
            }
            acc += vals[i];
        }
        atomicAdd(&out[(size_t)curg * OUTW + off + c], acc);
    }
}

// raw-x pooling (layer 0 only) — reads ORIGINAL fp32 x (no quantization)
__device__ void poolx_phase(const float* __restrict__ src, float* __restrict__ out,
                            const int* __restrict__ gids) {
    int c = threadIdx.x;
    if (c >= DINF) return;
    const int nch = NN / BNP_CH;
    for (int cc = blockIdx.x; cc < nch; cc += gridDim.x) {
        int r0 = cc * BNP_CH;
        float vals[BNP_CH];
        int gv[BNP_CH];
#pragma unroll
        for (int i = 0; i < BNP_CH; i++) {
            vals[i] = src[(size_t)(r0 + i) * DINF + c];
            gv[i] = gids[r0 + i];
        }
        int curg = gv[0];
        float acc = 0.f;
#pragma unroll
        for (int i = 0; i < BNP_CH; i++) {
            if (gv[i] != curg) {
                atomicAdd(&out[(size_t)curg * OUTW + c], acc);
                acc = 0.f;
                curg = gv[i];
            }
            acc += vals[i];
        }
        atomicAdd(&out[(size_t)curg * OUTW + c], acc);
    }
}

// ---------------- fused layer kernel ----------------------------------------
__global__ __launch_bounds__(256, 3)
void k_layer(const float* __restrict__ xraw, const float* __restrict__ epsv, int li, int K1,
             const uint32_t* __restrict__ wpk1, const float* __restrict__ b1,
             const uint32_t* __restrict__ wpk2, const float* __restrict__ b2,
             const float* __restrict__ ga, const float* __restrict__ bea,
             const float* __restrict__ gb, const float* __restrict__ bbb,
             const int* __restrict__ gids, float* __restrict__ out,
             int off, int write_h, int do_poolx) {
    __shared__ GemmSmem gsm;

    // phase A: spmm over fp16 features (+ fp32 poolx on layer 0)
    {
        float se = 1.0f + epsv[li];
        if (li == 0) spmm_phase<DINF / 4>(g_xh, g_apk, se);
        else         spmm_phase<DHF / 4>(g_hh, g_apk, se);
        if (do_poolx) poolx_phase(xraw, out, gids);
    }
    grid_sync();

    // phase B: GEMM1 (packed A) -> mid + stats[2l]
    gemm_phase<1>(gsm, nullptr, g_apk, wpk1, b1, g_mid, K1,
                  nullptr, nullptr, nullptr, nullptr,
                  g_sum[2 * li], g_sumsq[2 * li]);
    grid_sync();

    // phase C: BN-fold + GEMM2 (fp32 A=mid) -> rep + stats[2l+1]
    gemm_phase<0>(gsm, g_mid, nullptr, wpk2, b2, g_rep, DHF,
                  ga, bea, g_sum[2 * li], g_sumsq[2 * li],
                  g_sum[2 * li + 1], g_sumsq[2 * li + 1]);
    grid_sync();

    // phase D: BN + ReLU + pool (+ packed-fp16 h for layers 0..2)
    bnpool_phase(g_rep, out, off, gb, bbb, gids, 2 * li + 1, write_h);
}

// ---------------- launch ---------------------------------------------------
extern "C" void kernel_launch(void* const* d_in, const int* in_sizes, int n_in,
                              void* d_out, int out_size) {
    const float* x     = (const float*)d_in[0];
    const int*   erow  = (const int*)d_in[1];
    const int*   ecol  = (const int*)d_in[2];
    const int*   gid   = (const int*)d_in[3];
    const float* eps   = (const float*)d_in[4];
    const float* w1_0  = (const float*)d_in[5];
    const float* b1_0  = (const float*)d_in[6];
    const float* g1_0  = (const float*)d_in[7];
    const float* be1_0 = (const float*)d_in[8];
    const float* w2_0  = (const float*)d_in[9];
    const float* b2_0  = (const float*)d_in[10];
    const float* gbn_0 = (const float*)d_in[11];
    const float* bbn_0 = (const float*)d_in[12];
    const float* w1_r  = (const float*)d_in[13];
    const float* b1_r  = (const float*)d_in[14];
    const float* g1_r  = (const float*)d_in[15];
    const float* be1_r = (const float*)d_in[16];
    const float* w2_r  = (const float*)d_in[17];
    const float* b2_r  = (const float*)d_in[18];
    const float* gbn_r = (const float*)d_in[19];
    const float* bbn_r = (const float*)d_in[20];
    float* out = (float*)d_out;

    int E = in_sizes[1];

    uint32_t *wpk;
    cudaGetSymbolAddress((void**)&wpk, g_wpk);

    const int scan_smem = (NN + 1024) * (int)sizeof(int);
    cudaFuncSetAttribute(k_scan_big, cudaFuncAttributeMaxDynamicSharedMemorySize, scan_smem);

    int dev = 0;
    cudaGetDevice(&dev);
    int nsm = 0;
    cudaDeviceGetAttribute(&nsm, cudaDevAttrMultiProcessorCount, dev);
    int occ = 0;
    cudaOccupancyMaxActiveBlocksPerMultiprocessor(&occ, k_layer, 256, 0);
    if (occ < 1) occ = 1;
    const int lgrid = nsm * occ;

    k_packw<<<WPAIRS, DHF>>>(w1_0, w2_0, w1_r, w2_r, x, out, out_size);
    k_hist<<<(E + 255) / 256, 256>>>(erow, E);
    k_scan_big<<<1, 1024, scan_smem>>>();
    k_scatter<<<(E + 255) / 256, 256>>>(erow, ecol, E);

    const int woff_g1[NLAY] = {0, 164, 228, 292};
    const int woff_g2[NLAY] = {100, 356, 420, 484};

    for (int l = 0; l < NLAY; l++) {
        const float *ba, *ga, *bea, *bb, *gb, *bbb;
        int K1;
        if (l == 0) {
            K1 = DINF;
            ba = b1_0; ga = g1_0; bea = be1_0;
            bb = b2_0; gb = gbn_0; bbb = bbn_0;
        } else {
            K1 = DHF;
            int o1 = (l - 1) * DHF;
            ba = b1_r + o1; ga = g1_r + o1; bea = be1_r + o1;
            bb = b2_r + o1; gb = gbn_r + o1; bbb = bbn_r + o1;
        }
        k_layer<<<lgrid, 256>>>(x, eps, l, K1,
                                wpk + woff_g1[l] * DHF, ba,
                                wpk + woff_g2[l] * DHF, bb,
                                ga, bea, gb, bbb,
                                gid, out, DINF + l * DHF,
                                (l < NLAY - 1) ? 1 : 0,
                                (l == 0) ? 1 : 0);
    }
}

// round 15
// speedup vs baseline: 1.0585x; 1.0585x over previous
#include <cuda_runtime.h>
#include <cuda_fp16.h>
#include <cstdint>

// Problem constants (fixed-shape problem)
#define NN      50000
#define EE_MAX  800000
#define GG      128
#define DINF    200
#define DHF     128
#define NLAY    4
#define BN_EPS  1e-5f
#define OUTW    (DINF + NLAY * DHF)   // 712
#define WPAIRS  548
#define APK_W   50
#define NTILES  ((NN + 63) / 64)      // 782
#define BNP_CH  16                    // rows per bnpool chunk

// ---------------- scratch (device globals; no allocation allowed) ----------
__device__ uint4    g_apk    [NN * APK_W];
__device__ float    g_mid    [NN * DHF];
__device__ float    g_rep    [NN * DHF];
__device__ float    g_h      [NN * DHF];
__device__ int      g_cnt    [2 * NN];
__device__ int      g_rowptr [NN + 1];
__device__ int      g_colidx [EE_MAX];
__device__ float    g_sum    [2 * NLAY][DHF];
__device__ float    g_sumsq  [2 * NLAY][DHF];
__device__ uint32_t g_wpk    [WPAIRS * DHF];       // fp16x2 of W pair-rows
__device__ unsigned g_bar_cnt;
__device__ unsigned g_bar_gen;

// ---------------- device-wide barrier (all blocks resident) ----------------
__device__ __forceinline__ void grid_sync() {
    __syncthreads();
    if (threadIdx.x == 0) {
        unsigned gen = *(volatile unsigned*)&g_bar_gen;
        __threadfence();
        unsigned ticket = atomicAdd(&g_bar_cnt, 1u);
        if (ticket == gridDim.x - 1) {
            g_bar_cnt = 0u;
            __threadfence();
            atomicAdd(&g_bar_gen, 1u);
        } else {
            while (*(volatile unsigned*)&g_bar_gen == gen) __nanosleep(64);
        }
        __threadfence();
    }
    __syncthreads();
}

// ---------------- fp16 hi/lo split helpers ---------------------------------
__device__ __forceinline__ uint32_t pack_f16(float v0, float v1, float& rem0, float& rem1) {
    __half h0 = __float2half_rn(v0);
    __half h1 = __float2half_rn(v1);
    rem0 = v0 - __half2float(h0);
    rem1 = v1 - __half2float(h1);
    return ((uint32_t)__half_as_ushort(h1) << 16) | (uint32_t)__half_as_ushort(h0);
}
__device__ __forceinline__ uint32_t pack_f16_rn(float v0, float v1) {
    __half2 p = __floats2half2_rn(v0, v1);   // .x = v0 (low half)
    return *(uint32_t*)&p;
}

// -------- weight prepack (fp16) + hist zero + out zero ---------------------
__global__ void k_packw(const float* __restrict__ w1_0, const float* __restrict__ w2_0,
                        const float* __restrict__ w1_r, const float* __restrict__ w2_r,
                        float* __restrict__ out, int out_n) {
    int b = blockIdx.x;
    int c = threadIdx.x;
    int gtid = b * DHF + c;
    for (int i = gtid; i < NN; i += WPAIRS * DHF) g_cnt[i] = 0;
    for (int i = gtid; i < out_n; i += WPAIRS * DHF) out[i] = 0.f;

    const float* src;
    int kp;
    if (b < 100)      { src = w1_0; kp = b; }
    else if (b < 164) { src = w2_0; kp = b - 100; }
    else {
        int r = b - 164;
        if (r < 192) { src = w1_r + (r / 64) * DHF * DHF; kp = r % 64; }
        else { r -= 192; src = w2_r + (r / 64) * DHF * DHF; kp = r % 64; }
    }
    float v0 = src[(size_t)(2 * kp) * DHF + c];
    float v1 = src[(size_t)(2 * kp + 1) * DHF + c];
    g_wpk[b * DHF + c] = pack_f16_rn(v0, v1);
}

// ---------------- CSR build ------------------------------------------------
__global__ void k_hist(const int* __restrict__ erow, int E) {
    int e = blockIdx.x * blockDim.x + threadIdx.x;
    if (e < E) atomicAdd(&g_cnt[erow[e]], 1);
}

__global__ void k_scan_big() {
    extern __shared__ int sc[];
    int* part = sc + NN;
    const int T = 1024;
    int t = threadIdx.x;

    if (t < DHF) {
        for (int l = 0; l < 2 * NLAY; l++) { g_sum[l][t] = 0.f; g_sumsq[l][t] = 0.f; }
    }
    for (int i = t; i < NN; i += T) {
        sc[i] = g_cnt[i];
        g_cnt[NN + i] = 0;
    }
    __syncthreads();

    const int C = (NN + T - 1) / T;
    int base = t * C;
    int s = 0;
    for (int j = 0; j < C; j++) {
        int i = base + j;
        if (i < NN) s += sc[i];
    }
    part[t] = s;
    __syncthreads();
    for (int off = 1; off < T; off <<= 1) {
        int v = (t >= off) ? part[t - off] : 0;
        __syncthreads();
        part[t] += v;
        __syncthreads();
    }
    int pre = (t > 0) ? part[t - 1] : 0;
    for (int j = 0; j < C; j++) {
        int i = base + j;
        if (i < NN) {
            int c = sc[i];
            sc[i] = pre;
            pre += c;
        }
    }
    __syncthreads();
    for (int i = t; i < NN; i += T) g_rowptr[i] = sc[i];
    if (t == T - 1) g_rowptr[NN] = pre;
}

__global__ void k_scatter(const int* __restrict__ erow, const int* __restrict__ ecol, int E) {
    int e = blockIdx.x * blockDim.x + threadIdx.x;
    if (e < E) {
        int r = erow[e];
        int p = g_rowptr[r] + atomicAdd(&g_cnt[NN + r], 1);
        g_colidx[p] = ecol[e];
    }
}

// ---------------- fused layer kernel phases ---------------------------------
__device__ __forceinline__ void mma16(float* c, const uint32_t* a, const uint32_t* b) {
    asm volatile(
        "mma.sync.aligned.m16n8k16.row.col.f32.f16.f16.f32 "
        "{%0,%1,%2,%3}, {%4,%5,%6,%7}, {%8,%9}, {%0,%1,%2,%3};"
        : "+f"(c[0]), "+f"(c[1]), "+f"(c[2]), "+f"(c[3])
        : "r"(a[0]), "r"(a[1]), "r"(a[2]), "r"(a[3]), "r"(b[0]), "r"(b[1]));
}

struct GemmSmem {
    uint32_t ash[2][8][72], asl[2][8][72];
    uint32_t wsh[2][8][136];
    float strs[DHF], strh[DHF];
};

// phase A: spmm (warp per node, strided), 8-edge gather unroll (deep MLP)
template <int D4>
__device__ void spmm_phase(const float* __restrict__ hin, uint4* __restrict__ pout,
                           float se) {
    const int S = (D4 + 31) / 32;
    int lane = threadIdx.x & 31;
    int wstride = gridDim.x * 8;
    for (int wid = blockIdx.x * 8 + (threadIdx.x >> 5); wid < NN; wid += wstride) {
        const float4* selfr = (const float4*)hin + (size_t)wid * D4;
        float4 acc[S];
#pragma unroll
        for (int s = 0; s < S; s++) {
            int j = lane + 32 * s;
            if (j < D4) {
                float4 v = selfr[j];
                acc[s] = make_float4(v.x * se, v.y * se, v.z * se, v.w * se);
            } else acc[s] = make_float4(0.f, 0.f, 0.f, 0.f);
        }
        int e0 = g_rowptr[wid], e1 = g_rowptr[wid + 1];
        int e = e0;
        for (; e + 8 <= e1; e += 8) {
            const float4* rp[8];
#pragma unroll
            for (int u = 0; u < 8; u++)
                rp[u] = (const float4*)hin + (size_t)g_colidx[e + u] * D4;
#pragma unroll
            for (int s = 0; s < S; s++) {
                int j = lane + 32 * s;
                if (j < D4) {
                    float4 v0 = rp[0][j], v1 = rp[1][j], v2 = rp[2][j], v3 = rp[3][j];
                    float4 v4 = rp[4][j], v5 = rp[5][j], v6 = rp[6][j], v7 = rp[7][j];
                    acc[s].x += ((v0.x + v1.x) + (v2.x + v3.x)) + ((v4.x + v5.x) + (v6.x + v7.x));
                    acc[s].y += ((v0.y + v1.y) + (v2.y + v3.y)) + ((v4.y + v5.y) + (v6.y + v7.y));
                    acc[s].z += ((v0.z + v1.z) + (v2.z + v3.z)) + ((v4.z + v5.z) + (v6.z + v7.z));
                    acc[s].w += ((v0.w + v1.w) + (v2.w + v3.w)) + ((v4.w + v5.w) + (v6.w + v7.w));
                }
            }
        }
        for (; e + 2 <= e1; e += 2) {
            const float4* r0 = (const float4*)hin + (size_t)g_colidx[e] * D4;
            const float4* r1 = (const float4*)hin + (size_t)g_colidx[e + 1] * D4;
#pragma unroll
            for (int s = 0; s < S; s++) {
                int j = lane + 32 * s;
                if (j < D4) {
                    float4 v0 = r0[j], v1 = r1[j];
                    acc[s].x += v0.x + v1.x; acc[s].y += v0.y + v1.y;
                    acc[s].z += v0.z + v1.z; acc[s].w += v0.w + v1.w;
                }
            }
        }
        if (e < e1) {
            const float4* r = (const float4*)hin + (size_t)g_colidx[e] * D4;
#pragma unroll
            for (int s = 0; s < S; s++) {
                int j = lane + 32 * s;
                if (j < D4) {
                    float4 v = r[j];
                    acc[s].x += v.x; acc[s].y += v.y; acc[s].z += v.z; acc[s].w += v.w;
                }
            }
        }
        uint4* o = pout + (size_t)wid * D4;
#pragma unroll
        for (int s = 0; s < S; s++) {
            int j = lane + 32 * s;
            if (j < D4) {
                float r0, r1, r2, r3;
                uint32_t h01 = pack_f16(acc[s].x, acc[s].y, r0, r1);
                uint32_t h23 = pack_f16(acc[s].z, acc[s].w, r2, r3);
                o[j] = make_uint4(h01, h23, pack_f16_rn(r0, r1), pack_f16_rn(r2, r3));
            }
        }
    }
}

// GEMM phase: 64-row tiles strided by block; 2-term fp16 split.
// PACKED=1: A pre-packed (uint4 per 4k). PACKED=0: fp32 A + in-phase BN+ReLU.
template <int PACKED>
__device__ void gemm_phase(GemmSmem& sm,
                           const float* __restrict__ A, const uint4* __restrict__ Apk,
                           const uint32_t* __restrict__ wpk,
                           const float* __restrict__ bias, float* __restrict__ C, int K,
                           const float* __restrict__ bnga, const float* __restrict__ bnbe,
                           const float* __restrict__ psum, const float* __restrict__ psq,
                           float* __restrict__ osum, float* __restrict__ osumsq) {
    const int tid  = threadIdx.x;
    const int lane = tid & 31;
    const int wid  = tid >> 5;
    const int wr   = wid >> 2;
    const int wc   = wid & 3;
    const int gid  = lane >> 2;
    const int tq   = lane & 3;
    const int arA = tid & 63;
    const int kgA = tid >> 6;
    const int arW = tid & 127;
    const int kgW = tid >> 7;
    const int KP  = K >> 1;
    const int KP4 = K >> 2;
    const int T   = (K + 15) >> 4;

    if (!PACKED) {
        if (tid < DHF) {
            const float invN = 1.0f / NN;
            float m = psum[tid] * invN;
            float v = psq[tid] * invN - m * m;
            float sc = bnga[tid] * rsqrtf(v + BN_EPS);
            sm.strs[tid] = sc;
            sm.strh[tid] = bnbe[tid] - m * sc;
        }
        __syncthreads();
    }

    for (int tile = blockIdx.x; tile < NTILES; tile += gridDim.x) {
        const int row0 = tile * 64;
        const int grA  = row0 + arA;
        const bool rokA = (grA < NN);

        float acc[2][4][4];
#pragma unroll
        for (int mt = 0; mt < 2; mt++)
#pragma unroll
            for (int nt = 0; nt < 4; nt++)
#pragma unroll
                for (int j = 0; j < 4; j++) acc[mt][nt][j] = 0.f;

        float4 va;
        uint4 pa;
        uint32_t wk[4];

        auto prefetch = [&](int t) {
            if (PACKED) {
                int gp = t * 4 + kgA;
                pa = make_uint4(0u, 0u, 0u, 0u);
                if (rokA && gp < KP4) pa = Apk[(size_t)grA * KP4 + gp];
            } else {
                int gk0 = t * 16 + 4 * kgA;
                va = make_float4(0.f, 0.f, 0.f, 0.f);
                if (rokA && gk0 < K) va = *(const float4*)&A[(size_t)grA * K + gk0];
            }
#pragma unroll
            for (int j = 0; j < 4; j++) {
                int kp = t * 8 + kgW + 2 * j;
                wk[j] = (kp < KP) ? wpk[kp * DHF + arW] : 0u;
            }
        };

        auto stage = [&](int d, int k0) {
            if (PACKED) {
                sm.ash[d][2 * kgA][arA]     = pa.x;
                sm.ash[d][2 * kgA + 1][arA] = pa.y;
                sm.asl[d][2 * kgA][arA]     = pa.z;
                sm.asl[d][2 * kgA + 1][arA] = pa.w;
            } else {
                float a4[4] = {va.x, va.y, va.z, va.w};
                if (rokA) {
#pragma unroll
                    for (int j = 0; j < 4; j++) {
                        int gk = k0 + 4 * kgA + j;
                        a4[j] = (gk < K) ? fmaxf(a4[j] * sm.strs[gk] + sm.strh[gk], 0.f) : 0.f;
                    }
                }
#pragma unroll
                for (int p = 0; p < 2; p++) {
                    float r0f, r1f;
                    sm.ash[d][2 * kgA + p][arA] = pack_f16(a4[2 * p], a4[2 * p + 1], r0f, r1f);
                    sm.asl[d][2 * kgA + p][arA] = pack_f16_rn(r0f, r1f);
                }
            }
#pragma unroll
            for (int j = 0; j < 4; j++)
                sm.wsh[d][kgW + 2 * j][arW] = wk[j];
        };

        prefetch(0);
        stage(0, 0);
        __syncthreads();

        for (int t = 0; t < T; t++) {
            const int cur = t & 1;
            if (t + 1 < T) prefetch(t + 1);
            {
                uint32_t bh[4][2];
#pragma unroll
                for (int nt = 0; nt < 4; nt++) {
                    int col = wc * 32 + nt * 8 + gid;
                    bh[nt][0] = sm.wsh[cur][tq][col];
                    bh[nt][1] = sm.wsh[cur][tq + 4][col];
                }
#pragma unroll
                for (int mt = 0; mt < 2; mt++) {
                    int r0 = wr * 32 + mt * 16;
                    uint32_t ah[4], al[4];
                    ah[0] = sm.ash[cur][tq][r0 + gid];
                    ah[1] = sm.ash[cur][tq][r0 + gid + 8];
                    ah[2] = sm.ash[cur][tq + 4][r0 + gid];
                    ah[3] = sm.ash[cur][tq + 4][r0 + gid + 8];
                    al[0] = sm.asl[cur][tq][r0 + gid];
                    al[1] = sm.asl[cur][tq][r0 + gid + 8];
                    al[2] = sm.asl[cur][tq + 4][r0 + gid];
                    al[3] = sm.asl[cur][tq + 4][r0 + gid + 8];
#pragma unroll
                    for (int nt = 0; nt < 4; nt++) {
                        mma16(acc[mt][nt], ah, bh[nt]);   // hiA * W
                        mma16(acc[mt][nt], al, bh[nt]);   // loA * W
                    }
                }
            }
            if (t + 1 < T) stage((t + 1) & 1, (t + 1) * 16);
            __syncthreads();
        }

        // epilogue: bias, store, column stats
        float cs[4][2], cq[4][2];
#pragma unroll
        for (int nt = 0; nt < 4; nt++)
#pragma unroll
            for (int j = 0; j < 2; j++) { cs[nt][j] = 0.f; cq[nt][j] = 0.f; }

#pragma unroll
        for (int mt = 0; mt < 2; mt++) {
            int rbase = row0 + wr * 32 + mt * 16;
#pragma unroll
            for (int nt = 0; nt < 4; nt++) {
                int colb = wc * 32 + nt * 8 + 2 * tq;
                float b0 = bias[colb], b1 = bias[colb + 1];
                int r1 = rbase + gid;
                int r2 = rbase + gid + 8;
                if (r1 < NN) {
                    float v0 = acc[mt][nt][0] + b0;
                    float v1 = acc[mt][nt][1] + b1;
                    *(float2*)&C[(size_t)r1 * 128 + colb] = make_float2(v0, v1);
                    cs[nt][0] += v0; cq[nt][0] += v0 * v0;
                    cs[nt][1] += v1; cq[nt][1] += v1 * v1;
                }
                if (r2 < NN) {
                    float v0 = acc[mt][nt][2] + b0;
                    float v1 = acc[mt][nt][3] + b1;
                    *(float2*)&C[(size_t)r2 * 128 + colb] = make_float2(v0, v1);
                    cs[nt][0] += v0; cq[nt][0] += v0 * v0;
                    cs[nt][1] += v1; cq[nt][1] += v1 * v1;
                }
            }
        }
#pragma unroll
        for (int nt = 0; nt < 4; nt++)
#pragma unroll
            for (int j = 0; j < 2; j++) {
                float s = cs[nt][j], q = cq[nt][j];
                s += __shfl_xor_sync(0xffffffffu, s, 4);
                s += __shfl_xor_sync(0xffffffffu, s, 8);
                s += __shfl_xor_sync(0xffffffffu, s, 16);
                q += __shfl_xor_sync(0xffffffffu, q, 4);
                q += __shfl_xor_sync(0xffffffffu, q, 8);
                q += __shfl_xor_sync(0xffffffffu, q, 16);
                if (gid == 0) {
                    int col = wc * 32 + nt * 8 + 2 * tq + j;
                    atomicAdd(&osum[col], s);
                    atomicAdd(&osumsq[col], q);
                }
            }
        __syncthreads();
    }
}

// phase D: BN+ReLU+pool, 16-row chunks, two chunks per block pass
__device__ void bnpool_phase(const float* __restrict__ rep, float* __restrict__ h,
                             float* __restrict__ out, int off,
                             const float* __restrict__ gamma, const float* __restrict__ beta,
                             const int* __restrict__ gids, int slot, int write_h) {
    int c = threadIdx.x & 127;
    int half = threadIdx.x >> 7;
    const float invN = 1.0f / NN;
    float m = g_sum[slot][c] * invN;
    float v = g_sumsq[slot][c] * invN - m * m;
    float sc = gamma[c] * rsqrtf(v + BN_EPS);
    float sh = beta[c] - m * sc;

    const int nch = NN / BNP_CH;   // 3125 exact
    for (int cc = blockIdx.x * 2 + half; cc < nch; cc += gridDim.x * 2) {
        int r0 = cc * BNP_CH;
        float vals[BNP_CH];
        int gv[BNP_CH];
#pragma unroll
        for (int i = 0; i < BNP_CH; i++) {
            vals[i] = rep[(size_t)(r0 + i) * DHF + c];
            gv[i] = gids[r0 + i];
        }
#pragma unroll
        for (int i = 0; i < BNP_CH; i++)
            vals[i] = fmaxf(vals[i] * sc + sh, 0.f);
        if (write_h) {
#pragma unroll
            for (int i = 0; i < BNP_CH; i++)
                h[(size_t)(r0 + i) * DHF + c] = vals[i];
        }
        int curg = gv[0];
        float acc = 0.f;
#pragma unroll
        for (int i = 0; i < BNP_CH; i++) {
            if (gv[i] != curg) {
                atomicAdd(&out[(size_t)curg * OUTW + off + c], acc);
                acc = 0.f;
                curg = gv[i];
            }
            acc += vals[i];
        }
        atomicAdd(&out[(size_t)curg * OUTW + off + c], acc);
    }
}

// raw-x pooling (layer 0 only), 16-row chunks strided
__device__ void poolx_phase(const float* __restrict__ src, float* __restrict__ out,
                            const int* __restrict__ gids) {
    int c = threadIdx.x;
    if (c >= DINF) return;
    const int nch = NN / BNP_CH;
    for (int cc = blockIdx.x; cc < nch; cc += gridDim.x) {
        int r0 = cc * BNP_CH;
        float vals[BNP_CH];
        int gv[BNP_CH];
#pragma unroll
        for (int i = 0; i < BNP_CH; i++) {
            vals[i] = src[(size_t)(r0 + i) * DINF + c];
            gv[i] = gids[r0 + i];
        }
        int curg = gv[0];
        float acc = 0.f;
#pragma unroll
        for (int i = 0; i < BNP_CH; i++) {
            if (gv[i] != curg) {
                atomicAdd(&out[(size_t)curg * OUTW + c], acc);
                acc = 0.f;
                curg = gv[i];
            }
            acc += vals[i];
        }
        atomicAdd(&out[(size_t)curg * OUTW + c], acc);
    }
}

// ---------------- fused layer kernel ----------------------------------------
__global__ __launch_bounds__(256, 3)
void k_layer(const float* __restrict__ hin, const float* __restrict__ epsv, int li, int K1,
             const uint32_t* __restrict__ wpk1, const float* __restrict__ b1,
             const uint32_t* __restrict__ wpk2, const float* __restrict__ b2,
             const float* __restrict__ ga, const float* __restrict__ bea,
             const float* __restrict__ gb, const float* __restrict__ bbb,
             const int* __restrict__ gids, float* __restrict__ out,
             int off, int write_h, int do_poolx) {
    __shared__ GemmSmem gsm;

    // phase A: spmm (+ poolx on layer 0)
    {
        float se = 1.0f + epsv[li];
        if (li == 0) spmm_phase<DINF / 4>(hin, g_apk, se);
        else         spmm_phase<DHF / 4>(hin, g_apk, se);
        if (do_poolx) poolx_phase(hin, out, gids);
    }
    grid_sync();

    // phase B: GEMM1 (packed A) -> mid + stats[2l]
    gemm_phase<1>(gsm, nullptr, g_apk, wpk1, b1, g_mid, K1,
                  nullptr, nullptr, nullptr, nullptr,
                  g_sum[2 * li], g_sumsq[2 * li]);
    grid_sync();

    // phase C: BN-fold + GEMM2 (fp32 A=mid) -> rep + stats[2l+1]
    gemm_phase<0>(gsm, g_mid, nullptr, wpk2, b2, g_rep, DHF,
                  ga, bea, g_sum[2 * li], g_sumsq[2 * li],
                  g_sum[2 * li + 1], g_sumsq[2 * li + 1]);
    grid_sync();

    // phase D: BN + ReLU + pool (+ write h for layers 0..2)
    bnpool_phase(g_rep, g_h, out, off, gb, bbb, gids, 2 * li + 1, write_h);
}

// ---------------- launch ---------------------------------------------------
extern "C" void kernel_launch(void* const* d_in, const int* in_sizes, int n_in,
                              void* d_out, int out_size) {
    const float* x     = (const float*)d_in[0];
    const int*   erow  = (const int*)d_in[1];
    const int*   ecol  = (const int*)d_in[2];
    const int*   gid   = (const int*)d_in[3];
    const float* eps   = (const float*)d_in[4];
    const float* w1_0  = (const float*)d_in[5];
    const float* b1_0  = (const float*)d_in[6];
    const float* g1_0  = (const float*)d_in[7];
    const float* be1_0 = (const float*)d_in[8];
    const float* w2_0  = (const float*)d_in[9];
    const float* b2_0  = (const float*)d_in[10];
    const float* gbn_0 = (const float*)d_in[11];
    const float* bbn_0 = (const float*)d_in[12];
    const float* w1_r  = (const float*)d_in[13];
    const float* b1_r  = (const float*)d_in[14];
    const float* g1_r  = (const float*)d_in[15];
    const float* be1_r = (const float*)d_in[16];
    const float* w2_r  = (const float*)d_in[17];
    const float* b2_r  = (const float*)d_in[18];
    const float* gbn_r = (const float*)d_in[19];
    const float* bbn_r = (const float*)d_in[20];
    float* out = (float*)d_out;

    int E = in_sizes[1];

    float *hbuf;
    uint32_t *wpk;
    cudaGetSymbolAddress((void**)&hbuf, g_h);
    cudaGetSymbolAddress((void**)&wpk,  g_wpk);

    const int scan_smem = (NN + 1024) * (int)sizeof(int);
    cudaFuncSetAttribute(k_scan_big, cudaFuncAttributeMaxDynamicSharedMemorySize, scan_smem);

    int dev = 0;
    cudaGetDevice(&dev);
    int nsm = 0;
    cudaDeviceGetAttribute(&nsm, cudaDevAttrMultiProcessorCount, dev);
    int occ = 0;
    cudaOccupancyMaxActiveBlocksPerMultiprocessor(&occ, k_layer, 256, 0);
    if (occ < 1) occ = 1;
    const int lgrid = nsm * occ;

    k_packw<<<WPAIRS, DHF>>>(w1_0, w2_0, w1_r, w2_r, out, out_size);
    k_hist<<<(E + 255) / 256, 256>>>(erow, E);
    k_scan_big<<<1, 1024, scan_smem>>>();
    k_scatter<<<(E + 255) / 256, 256>>>(erow, ecol, E);

    const int woff_g1[NLAY] = {0, 164, 228, 292};
    const int woff_g2[NLAY] = {100, 356, 420, 484};

    for (int l = 0; l < NLAY; l++) {
        const float *hin, *ba, *ga, *bea, *bb, *gb, *bbb;
        int K1;
        if (l == 0) {
            hin = x; K1 = DINF;
            ba = b1_0; ga = g1_0; bea = be1_0;
            bb = b2_0; gb = gbn_0; bbb = bbn_0;
        } else {
            hin = hbuf; K1 = DHF;
            int o1 = (l - 1) * DHF;
            ba = b1_r + o1; ga = g1_r + o1; bea = be1_r + o1;
            bb = b2_r + o1; gb = gbn_r + o1; bbb = bbn_r + o1;
        }
        k_layer<<<lgrid, 256>>>(hin, eps, l, K1,
                                wpk + woff_g1[l] * DHF, ba,
                                wpk + woff_g2[l] * DHF, bb,
                                ga, bea, gb, bbb,
                                gid, out, DINF + l * DHF,
                                (l < NLAY - 1) ? 1 : 0,
                                (l == 0) ? 1 : 0);
    }
}